// round 17
// baseline (speedup 1.0000x reference)
#include <cuda_runtime.h>
#include <cuda_fp16.h>
#include <cstdint>

// Problem constants
#define BATCH  16
#define CCH    384
#define HW     4096
#define NHEADS 12
#define DHEAD  32
#define QKV_C  1152

#define BK     64
#define NCHUNK (CCH / BK)   // 6

// ---------------------------------------------------------------------------
// Device-global scratch (no cudaMalloc allowed)
// ---------------------------------------------------------------------------
__device__ __align__(256) __half g_qkv[(size_t)BATCH * HW * QKV_C]; // fp16, q pre-scaled
__device__ __align__(256) __half g_o [(size_t)BATCH * HW * CCH];    // attn out fp16
__device__ __align__(256) __half g_wq_h[QKV_C * CCH];
__device__ __align__(256) __half g_wp_h[CCH * CCH];

// ---------------------------------------------------------------------------
// Helpers
// ---------------------------------------------------------------------------
__device__ __forceinline__ uint32_t smem_u32(const void* p) {
    uint32_t a;
    asm("{ .reg .u64 t; cvta.to.shared.u64 t, %1; cvt.u32.u64 %0, t; }"
        : "=r"(a) : "l"(p));
    return a;
}

__device__ __forceinline__ uint32_t pack_half2(float a, float b) {
    __half ha = __float2half_rn(a), hb = __float2half_rn(b);
    uint16_t ua = *reinterpret_cast<uint16_t*>(&ha);
    uint16_t ub = *reinterpret_cast<uint16_t*>(&hb);
    return (uint32_t)ua | ((uint32_t)ub << 16);
}

// 32-col tile swizzle (attn): rows of 32 halves (64B), 4x16B chunks
__device__ __forceinline__ uint32_t swz(uint32_t row, uint32_t c16) {
    return row * 64u + ((c16 ^ ((row >> 1) & 3u)) * 16u);
}

// 64-col tile swizzle (gemm B): rows of 64 halves (128B), 8x16B chunks
__device__ __forceinline__ uint32_t swz128(uint32_t row, uint32_t c16) {
    return row * 128u + ((c16 ^ (row & 7u)) * 16u);
}

// A32 staging tile: 64 rows x 128 fp32 (512B rows, 32 x 16B chunks)
__device__ __forceinline__ uint32_t swzA32(uint32_t row, uint32_t c16) {
    return row * 512u + ((c16 ^ (row & 31u)) * 16u);
}

// A16 tile (k-major [k=64][m=128]): 256B rows, 16 x 16B chunks
__device__ __forceinline__ uint32_t swzA16(uint32_t row, uint32_t c16) {
    return row * 256u + ((c16 ^ (row & 15u) ^ (((row >> 4) & 1u) << 3)) * 16u);
}

__device__ __forceinline__ void ldm_x4(uint32_t* r, uint32_t addr) {
    asm volatile("ldmatrix.sync.aligned.m8n8.x4.shared.b16 {%0,%1,%2,%3}, [%4];"
                 : "=r"(r[0]), "=r"(r[1]), "=r"(r[2]), "=r"(r[3]) : "r"(addr));
}

__device__ __forceinline__ void ldm_x4_trans(uint32_t* r, uint32_t addr) {
    asm volatile("ldmatrix.sync.aligned.m8n8.x4.trans.shared.b16 {%0,%1,%2,%3}, [%4];"
                 : "=r"(r[0]), "=r"(r[1]), "=r"(r[2]), "=r"(r[3]) : "r"(addr));
}

__device__ __forceinline__ void mma16816h(float* c, const uint32_t* a, const uint32_t* b) {
    asm volatile(
        "mma.sync.aligned.m16n8k16.row.col.f32.f16.f16.f32 "
        "{%0,%1,%2,%3}, {%4,%5,%6,%7}, {%8,%9}, {%0,%1,%2,%3};"
        : "+f"(c[0]), "+f"(c[1]), "+f"(c[2]), "+f"(c[3])
        : "r"(a[0]), "r"(a[1]), "r"(a[2]), "r"(a[3]), "r"(b[0]), "r"(b[1]));
}

#define CP_ASYNC16(dst, src) \
    asm volatile("cp.async.cg.shared.global [%0], [%1], 16;" :: "r"(dst), "l"(src))
#define CP_COMMIT() asm volatile("cp.async.commit_group;")
#define CP_WAIT0()  asm volatile("cp.async.wait_group 0;")
#define CP_WAIT1()  asm volatile("cp.async.wait_group 1;")

// load one ROWSx64 fp16 tile (row stride CCH) into swizzled smem via cp.async
template<int ROWS>
__device__ __forceinline__ void load_tileR_async(const __half* __restrict__ src,
                                                 int row0, int k0, uint32_t dst, int tid) {
    #pragma unroll
    for (int j = 0; j < ROWS / 16; j++) {
        int c   = tid + j * 128;
        int row = c >> 3, c16 = c & 7;
        const __half* g = src + (size_t)(row0 + row) * CCH + k0 + c16 * 8;
        CP_ASYNC16(dst + swz128((uint32_t)row, (uint32_t)c16), g);
    }
}

// load 64(k-rows) x 128(pix) fp32 chunk of x into swizzled A32 staging
__device__ __forceinline__ void load_a32_async(const float* __restrict__ xb,
                                               int m0, int k0, uint32_t dst, int tid) {
    #pragma unroll
    for (int j = 0; j < 16; j++) {
        int c   = tid + j * 128;
        int row = c >> 5, c16 = c & 31;
        const float* g = xb + (size_t)(k0 + row) * HW + m0 + c16 * 4;
        CP_ASYNC16(dst + swzA32((uint32_t)row, (uint32_t)c16), g);
    }
}

// ---------------------------------------------------------------------------
// Weight fp16 conversion (single rounding), grid-stride
// ---------------------------------------------------------------------------
__global__ __launch_bounds__(256) void weight_half_kernel(const float* __restrict__ wq,
                                                          const float* __restrict__ wp)
{
    int stride = gridDim.x * 256;
    for (int i = blockIdx.x * 256 + threadIdx.x; i < QKV_C * CCH; i += stride)
        g_wq_h[i] = __float2half_rn(wq[i]);
    for (int i = blockIdx.x * 256 + threadIdx.x; i < CCH * CCH; i += stride)
        g_wp_h[i] = __float2half_rn(wp[i]);
}

// ---------------------------------------------------------------------------
// QKV GEMM with fused x transpose+convert.
// D[pix(128)][och(128)] = x^T[pix][cch] . W[och][cch]^T
// A path: cp.async fp32 x [c][pix] chunk -> staged -> convert to fp16 [k][m]
//         tile -> ldmatrix.trans for A fragments.
// 4 warps, warp tile 64x64. BK=64, 2-stage pipeline + single A16 buffer.
// Out: g_qkv fp16 [b][pix][1152], q cols pre-scaled by 1/sqrt(d).
// ---------------------------------------------------------------------------
#define Q_A32_ST   32768
#define Q_B_OFF    65536
#define Q_B_ST     16384
#define Q_A16_OFF  98304
#define Q_SMEM     114688

__global__ __launch_bounds__(128, 2)
void qkv_gemm_fused_kernel(const float* __restrict__ x, const float* __restrict__ bias)
{
    extern __shared__ __align__(128) char smem[];
    const uint32_t sbase = smem_u32(smem);
    const int tid = threadIdx.x, wid = tid >> 5, lane = tid & 31;
    const int warp_m = wid & 1;
    const int warp_n = wid >> 1;

    const int b  = blockIdx.z;
    const int n0 = blockIdx.x * 128;   // och tile (x fastest -> A reuse in L2)
    const int m0 = blockIdx.y * 128;   // pixel tile

    const float* xb = x + (size_t)b * CCH * HW;

    float acc[4][8][4] = {};

    // prologue: chunks 0,1
    #pragma unroll
    for (int i = 0; i < 2; i++) {
        load_a32_async(xb, m0, i * BK, sbase + i * Q_A32_ST, tid);
        load_tileR_async<128>(g_wq_h, n0, i * BK, sbase + Q_B_OFF + i * Q_B_ST, tid);
        CP_COMMIT();
    }
    CP_WAIT1();
    __syncthreads();

    const int lrow = lane & 7;
    const int lblk = lane >> 3;
    const int crow = tid & 63;         // convert: k-row
    const int cpart = tid >> 6;        // convert: m half

    #pragma unroll 1
    for (int i = 0; i < NCHUNK; i++) {
        const int s = i & 1;
        const uint32_t a32 = sbase + s * Q_A32_ST;
        const uint32_t a16 = sbase + Q_A16_OFF;
        const uint32_t sB  = sbase + Q_B_OFF + s * Q_B_ST;

        // ---- convert A32[s] -> A16 ([k][m] fp16) ----
        #pragma unroll
        for (int j = 0; j < 16; j++) {
            int lc = cpart * 16 + j;
            uint32_t raddr = a32 + swzA32((uint32_t)crow, (uint32_t)lc);
            float4 v;
            asm volatile("ld.shared.v4.f32 {%0,%1,%2,%3}, [%4];"
                         : "=f"(v.x), "=f"(v.y), "=f"(v.z), "=f"(v.w) : "r"(raddr));
            __half2 h0 = __floats2half2_rn(v.x, v.y);
            __half2 h1 = __floats2half2_rn(v.z, v.w);
            int c16m = cpart * 8 + (j >> 1);
            uint32_t waddr = a16 + swzA16((uint32_t)crow, (uint32_t)c16m) + (uint32_t)((j & 1) * 8);
            asm volatile("st.shared.v2.b32 [%0], {%1,%2};" :: "r"(waddr),
                         "r"(*reinterpret_cast<uint32_t*>(&h0)),
                         "r"(*reinterpret_cast<uint32_t*>(&h1)));
        }
        __syncthreads();

        // ---- mma: A via ldmatrix.trans on [k][m] tile, B normal ----
        #pragma unroll
        for (int ks = 0; ks < 4; ks++) {
            uint32_t Af[4][4];
            #pragma unroll
            for (int mt = 0; mt < 4; mt++) {
                uint32_t row = (uint32_t)(ks * 16 + (lblk >> 1) * 8 + lrow);
                uint32_t c16 = (uint32_t)(warp_m * 8 + mt * 2 + (lblk & 1));
                ldm_x4_trans(Af[mt], a16 + swzA16(row, c16));
            }
            uint32_t Bf[8][2];
            #pragma unroll
            for (int np = 0; np < 4; np++) {
                uint32_t row = (uint32_t)(warp_n * 64 + np * 16 + (lblk >> 1) * 8 + lrow);
                uint32_t c16 = (uint32_t)(ks * 2 + (lblk & 1));
                uint32_t r[4];
                ldm_x4(r, sB + swz128(row, c16));
                Bf[np*2][0] = r[0]; Bf[np*2][1] = r[1];
                Bf[np*2+1][0] = r[2]; Bf[np*2+1][1] = r[3];
            }
            #pragma unroll
            for (int mt = 0; mt < 4; mt++)
                #pragma unroll
                for (int nt = 0; nt < 8; nt++)
                    mma16816h(acc[mt][nt], Af[mt], Bf[nt]);
        }
        __syncthreads();     // stage s fully consumed (A32 by convert, B by ldm)

        if (i + 2 < NCHUNK) {
            load_a32_async(xb, m0, (i + 2) * BK, a32, tid);
            load_tileR_async<128>(g_wq_h, n0, (i + 2) * BK, sB, tid);
            CP_COMMIT();
        }
        if (i + 1 < NCHUNK) {
            if (i + 2 < NCHUNK) CP_WAIT1(); else CP_WAIT0();
            __syncthreads();
        }
    }

    // ---- epilogue: fp16 out [b][pix][1152]; bias; q cols scaled ----
    {
        constexpr int PADH = 136;
        const float SCALE = 0.17677669529663687f;
        __half* st = reinterpret_cast<__half*>(smem);   // [128][136]
        __syncthreads();
        #pragma unroll
        for (int mt = 0; mt < 4; mt++)
            #pragma unroll
            for (int nt = 0; nt < 8; nt++) {
                int ml = warp_m * 64 + mt * 16 + (lane >> 2);
                int nl = warp_n * 64 + nt * 8 + (lane & 3) * 2;
                int och = n0 + nl;
                float s  = (och < CCH) ? SCALE : 1.0f;
                float b0 = bias[och], b1 = bias[och + 1];
                *reinterpret_cast<uint32_t*>(&st[ml * PADH + nl]) =
                    pack_half2((acc[mt][nt][0] + b0) * s, (acc[mt][nt][1] + b1) * s);
                *reinterpret_cast<uint32_t*>(&st[(ml + 8) * PADH + nl]) =
                    pack_half2((acc[mt][nt][2] + b0) * s, (acc[mt][nt][3] + b1) * s);
            }
        __syncthreads();
        __half* outb = g_qkv + (size_t)b * HW * QKV_C;
        #pragma unroll
        for (int j = 0; j < 16; j++) {
            int fi  = tid + j * 128;
            int row = fi >> 4;
            int c16 = fi & 15;
            uint4 v = *reinterpret_cast<uint4*>(&st[row * PADH + c16 * 8]);
            *reinterpret_cast<uint4*>(&outb[(size_t)(m0 + row) * QKV_C + n0 + c16 * 8]) = v;
        }
    }
}

// ---------------------------------------------------------------------------
// Proj GEMM (R16-proven): CTA 64x128, 4 warps (2m x 2n), warp tile 32x64,
// 3 CTAs/SM, BK=64, 3-stage pipeline. A = g_o, B = w_proj -> fp32 out.
// ---------------------------------------------------------------------------
#define P_ST     24576
#define P_B_OFF  8192
#define P_SMEM   73728

__global__ __launch_bounds__(128, 3)
void proj_gemm_kernel(const float* __restrict__ bias, float* __restrict__ out_base)
{
    extern __shared__ __align__(128) char smem[];
    const uint32_t sbase = smem_u32(smem);
    const int tid = threadIdx.x, wid = tid >> 5, lane = tid & 31;
    const int warp_m = wid & 1;
    const int warp_n = wid >> 1;

    const int b  = blockIdx.z;
    const int n0 = blockIdx.x * 128;
    const int m0 = blockIdx.y * 64;

    const __half* A  = g_o + (size_t)b * HW * CCH;

    float acc[2][8][4] = {};

    #pragma unroll
    for (int i = 0; i < 2; i++) {
        const uint32_t sb = sbase + i * P_ST;
        load_tileR_async<64>(A, m0, i * BK, sb + 0, tid);
        load_tileR_async<128>(g_wp_h, n0, i * BK, sb + P_B_OFF, tid);
        CP_COMMIT();
    }
    CP_WAIT1();
    __syncthreads();

    const int lrow = lane & 7;
    const int lblk = lane >> 3;

    #pragma unroll 1
    for (int i = 0; i < NCHUNK; i++) {
        if (i + 2 < NCHUNK) {
            const uint32_t nb = sbase + ((i + 2) % 3) * P_ST;
            const int k0 = (i + 2) * BK;
            load_tileR_async<64>(A, m0, k0, nb + 0, tid);
            load_tileR_async<128>(g_wp_h, n0, k0, nb + P_B_OFF, tid);
            CP_COMMIT();
        }

        const uint32_t sA = sbase + (i % 3) * P_ST;
        const uint32_t sB = sA + P_B_OFF;

        #pragma unroll
        for (int ks = 0; ks < 4; ks++) {
            uint32_t Af[2][4];
            #pragma unroll
            for (int mt = 0; mt < 2; mt++) {
                uint32_t row = (uint32_t)(warp_m * 32 + mt * 16 + (lblk & 1) * 8 + lrow);
                uint32_t c16 = (uint32_t)(ks * 2 + (lblk >> 1));
                ldm_x4(Af[mt], sA + swz128(row, c16));
            }
            uint32_t Bf[8][2];
            #pragma unroll
            for (int np = 0; np < 4; np++) {
                uint32_t row = (uint32_t)(warp_n * 64 + np * 16 + (lblk >> 1) * 8 + lrow);
                uint32_t c16 = (uint32_t)(ks * 2 + (lblk & 1));
                uint32_t r[4];
                ldm_x4(r, sB + swz128(row, c16));
                Bf[np*2][0] = r[0]; Bf[np*2][1] = r[1];
                Bf[np*2+1][0] = r[2]; Bf[np*2+1][1] = r[3];
            }
            #pragma unroll
            for (int mt = 0; mt < 2; mt++)
                #pragma unroll
                for (int nt = 0; nt < 8; nt++)
                    mma16816h(acc[mt][nt], Af[mt], Bf[nt]);
        }

        if (i + 2 < NCHUNK)      CP_WAIT1();
        else if (i + 1 < NCHUNK) CP_WAIT0();
        __syncthreads();
    }

    // epilogue: stage 128(och) x 64(pix) fp32, coalesced store
    {
        constexpr int PAD = 68;
        float* st = reinterpret_cast<float*>(smem);
        #pragma unroll
        for (int mt = 0; mt < 2; mt++)
            #pragma unroll
            for (int nt = 0; nt < 8; nt++) {
                int ml = warp_m * 32 + mt * 16 + (lane >> 2);
                int nl = warp_n * 64 + nt * 8 + (lane & 3) * 2;
                st[nl * PAD + ml]           = acc[mt][nt][0];
                st[(nl + 1) * PAD + ml]     = acc[mt][nt][1];
                st[nl * PAD + ml + 8]       = acc[mt][nt][2];
                st[(nl + 1) * PAD + ml + 8] = acc[mt][nt][3];
            }
        __syncthreads();
        float* outb = out_base + (size_t)b * CCH * HW;
        #pragma unroll
        for (int j = 0; j < 16; j++) {
            int fi  = tid + j * 128;
            int row = fi >> 4;
            int c4  = (fi & 15) * 4;
            int och = n0 + row;
            float4 v = *reinterpret_cast<float4*>(&st[row * PAD + c4]);
            float bi = bias[och];
            v.x += bi; v.y += bi; v.z += bi; v.w += bi;
            *reinterpret_cast<float4*>(&outb[(size_t)och * HW + m0 + c4]) = v;
        }
    }
}

// ---------------------------------------------------------------------------
// Attention: 1 block = (b, head, window), 4 warps. All-fp16 operands.
// q pre-scaled by producer. S single-pass; P·V single-pass fp16 (P in [0,1]).
// Strided windows (faithful to reference).
// ---------------------------------------------------------------------------
__global__ __launch_bounds__(128) void attn_mma_kernel()
{
    __shared__ __align__(128) __half sq[64 * 32];
    __shared__ __align__(128) __half sk[64 * 32];
    __shared__ __align__(128) __half sv[64 * 32];

    const int wi   = blockIdx.x;
    const int head = blockIdx.y;
    const int b    = blockIdx.z;
    const int hh   = wi >> 3;
    const int ww   = wi & 7;
    const int tid  = threadIdx.x;
    const int wid  = tid >> 5;
    const int lane = tid & 31;

    const uint32_t aq = smem_u32(sq), ak = smem_u32(sk), av = smem_u32(sv);

    const __half* base = g_qkv + (size_t)b * HW * QKV_C + (size_t)head * DHEAD;

    #pragma unroll
    for (int it = 0; it < 6; it++) {
        int e   = tid + it * 128;
        int ten = e >> 8;
        int rem = e & 255;
        int tok = rem >> 2;
        int c16 = rem & 3;
        int wsh = tok >> 3, wsw = tok & 7;
        int pix = (wsh * 8 + hh) * 64 + wsw * 8 + ww;
        const __half* g = base + (size_t)pix * QKV_C + ten * CCH + c16 * 8;
        uint32_t dst = (ten == 0 ? aq : ten == 1 ? ak : av) + swz((uint32_t)tok, (uint32_t)c16);
        CP_ASYNC16(dst, g);
    }
    CP_COMMIT();
    CP_WAIT0();
    __syncthreads();

    const int lrow = lane & 7;
    const int lblk = lane >> 3;

    float acc[8][4] = {};
    #pragma unroll
    for (int ks = 0; ks < 2; ks++) {
        uint32_t Af[4];
        {
            uint32_t row = (uint32_t)(wid * 16 + (lblk & 1) * 8 + lrow);
            uint32_t c16 = (uint32_t)(ks * 2 + (lblk >> 1));
            ldm_x4(Af, aq + swz(row, c16));
        }
        uint32_t Bf[8][2];
        #pragma unroll
        for (int np = 0; np < 4; np++) {
            uint32_t row = (uint32_t)(np * 16 + (lblk >> 1) * 8 + lrow);
            uint32_t c16 = (uint32_t)(ks * 2 + (lblk & 1));
            uint32_t r[4];
            ldm_x4(r, ak + swz(row, c16));
            Bf[np*2][0] = r[0]; Bf[np*2][1] = r[1];
            Bf[np*2+1][0] = r[2]; Bf[np*2+1][1] = r[3];
        }
        #pragma unroll
        for (int nt = 0; nt < 8; nt++) mma16816h(acc[nt], Af, Bf[nt]);
    }

    float mx0 = -1e30f, mx1 = -1e30f;
    #pragma unroll
    for (int nt = 0; nt < 8; nt++) {
        mx0 = fmaxf(mx0, fmaxf(acc[nt][0], acc[nt][1]));
        mx1 = fmaxf(mx1, fmaxf(acc[nt][2], acc[nt][3]));
    }
    #pragma unroll
    for (int d = 1; d <= 2; d <<= 1) {
        mx0 = fmaxf(mx0, __shfl_xor_sync(0xffffffffu, mx0, d));
        mx1 = fmaxf(mx1, __shfl_xor_sync(0xffffffffu, mx1, d));
    }
    float s0 = 0.f, s1 = 0.f;
    #pragma unroll
    for (int nt = 0; nt < 8; nt++) {
        acc[nt][0] = __expf(acc[nt][0] - mx0);
        acc[nt][1] = __expf(acc[nt][1] - mx0);
        acc[nt][2] = __expf(acc[nt][2] - mx1);
        acc[nt][3] = __expf(acc[nt][3] - mx1);
        s0 += acc[nt][0] + acc[nt][1];
        s1 += acc[nt][2] + acc[nt][3];
    }
    #pragma unroll
    for (int d = 1; d <= 2; d <<= 1) {
        s0 += __shfl_xor_sync(0xffffffffu, s0, d);
        s1 += __shfl_xor_sync(0xffffffffu, s1, d);
    }
    const float inv0 = 1.f / s0, inv1 = 1.f / s1;

    float o[4][4] = {};
    #pragma unroll
    for (int j = 0; j < 4; j++) {
        uint32_t aP[4];
        aP[0] = pack_half2(acc[2*j][0],   acc[2*j][1]);
        aP[1] = pack_half2(acc[2*j][2],   acc[2*j][3]);
        aP[2] = pack_half2(acc[2*j+1][0], acc[2*j+1][1]);
        aP[3] = pack_half2(acc[2*j+1][2], acc[2*j+1][3]);

        uint32_t Bv[4][2];
        #pragma unroll
        for (int a = 0; a < 2; a++) {
            uint32_t row = (uint32_t)(16 * j + lrow + (lblk & 1) * 8);
            uint32_t c16 = (uint32_t)(2 * a + (lblk >> 1));
            uint32_t r[4];
            ldm_x4_trans(r, av + swz(row, c16));
            Bv[2*a][0] = r[0]; Bv[2*a][1] = r[1];
            Bv[2*a+1][0] = r[2]; Bv[2*a+1][1] = r[3];
        }
        #pragma unroll
        for (int nt = 0; nt < 4; nt++) mma16816h(o[nt], aP, Bv[nt]);
    }

    __syncthreads();
    {
        int r0 = 16 * wid + (lane >> 2);
        int cb = (lane & 3) * 2;
        #pragma unroll
        for (int nt = 0; nt < 4; nt++) {
            int d = nt * 8 + cb;
            *reinterpret_cast<uint32_t*>(&sq[r0 * 32 + d]) =
                pack_half2(o[nt][0] * inv0, o[nt][1] * inv0);
            *reinterpret_cast<uint32_t*>(&sq[(r0 + 8) * 32 + d]) =
                pack_half2(o[nt][2] * inv1, o[nt][3] * inv1);
        }
    }
    __syncthreads();
    {
        int tok  = tid >> 1;
        int half = tid & 1;
        int wsh = tok >> 3, wsw = tok & 7;
        int pixo = (hh * 8 + wsh) * 64 + ww * 8 + wsw;
        size_t off = ((size_t)b * HW + pixo) * CCH + head * DHEAD + half * 16;
        const uint4* s = reinterpret_cast<const uint4*>(&sq[tok * 32 + half * 16]);
        uint4* d = reinterpret_cast<uint4*>(g_o + off);
        d[0] = s[0];
        d[1] = s[1];
    }
}

// ---------------------------------------------------------------------------
extern "C" void kernel_launch(void* const* d_in, const int* in_sizes, int n_in,
                              void* d_out, int out_size)
{
    const float* x      = (const float*)d_in[0];
    const float* w_qkv  = (const float*)d_in[1];
    const float* b_qkv  = (const float*)d_in[2];
    const float* w_proj = (const float*)d_in[3];
    const float* b_proj = (const float*)d_in[4];
    float* out = (float*)d_out;
    (void)in_sizes; (void)n_in; (void)out_size;

    cudaFuncSetAttribute(qkv_gemm_fused_kernel,
                         cudaFuncAttributeMaxDynamicSharedMemorySize, Q_SMEM);
    cudaFuncSetAttribute(proj_gemm_kernel,
                         cudaFuncAttributeMaxDynamicSharedMemorySize, P_SMEM);

    weight_half_kernel<<<296, 256>>>(w_qkv, w_proj);

    dim3 g1(QKV_C / 128, HW / 128, BATCH);   // n fastest -> x-slice L2 reuse
    qkv_gemm_fused_kernel<<<g1, 128, Q_SMEM>>>(x, b_qkv);

    dim3 gA(64, NHEADS, BATCH);
    attn_mma_kernel<<<gA, 128>>>();

    dim3 g2(CCH / 128, HW / 64, BATCH);      // 3 x 64 x 16 = 3072 CTAs
    proj_gemm_kernel<<<g2, 128, P_SMEM>>>(b_proj, out);
}